// round 7
// baseline (speedup 1.0000x reference)
#include <cuda_runtime.h>
#include <cuda_bf16.h>
#include <cstdint>

// ============================================================================
// SelfAttention, mma.sync bf16x3-split, cp.async 3-stage pipelined GEMMs.
// R7: warp tile 64x32 (8 warps, 256 thr/CTA, 128x128 tile) -> MMA:LDSM 4:1,
// smem crossbar no longer co-binding with tensor pipe. QKV fused into one
// launch (grid.z selects Wq/Wk/Wv; VT via smem-staged transposed epilogue).
// ============================================================================

constexpr int S = 2048, D = 1024, NB = 4;
constexpr long SD  = (long)S * D;
constexpr long SSZ = (long)S * S;
constexpr long NX = (long)NB * S * D;
constexpr long NW = (long)D * D;
constexpr long NP = (long)NB * S * S;

constexpr long OXH = 0,        OXL = NX;
constexpr long OWQH = 2*NX,    OWQL = OWQH+NW, OWKH = OWQH+2*NW, OWKL = OWQH+3*NW,
               OWVH = OWQH+4*NW, OWVL = OWQH+5*NW;
constexpr long OQH = 2*NX+6*NW, OQL = OQH+NX, OKH = OQH+2*NX, OKL = OQH+3*NX,
               OVTH = OQH+4*NX, OVTL = OQH+5*NX;
constexpr long OPH = OQH+6*NX,  OPL = OPH+NP;
constexpr long NBF = OPL + NP;

__device__ __align__(128) __nv_bfloat16 g_bf[NBF];
__device__ float g_sc[NP];

constexpr int STAGE  = 64 * 1024;          // AH|AL|BH|BL x 16KB
constexpr int OFF_AH = 0, OFF_AL = 16384, OFF_BH = 32768, OFF_BL = 49152;
constexpr int NSTG   = 3;
constexpr int SMEM_DYN = NSTG * STAGE + 1024;

#define SWZ(o) ((o) ^ (((o) >> 3) & 0x70))

// ---------------------------------------------------------------- helpers
__device__ __forceinline__ uint32_t smem_u32(const void* p) {
    uint32_t a;
    asm("{ .reg .u64 t; cvta.to.shared.u64 t, %1; cvt.u32.u64 %0, t; }"
        : "=r"(a) : "l"(p));
    return a;
}
__device__ __forceinline__ void ldsm4(uint32_t* r, uint32_t addr) {
    asm volatile("ldmatrix.sync.aligned.m8n8.x4.shared.b16 {%0,%1,%2,%3}, [%4];"
                 : "=r"(r[0]), "=r"(r[1]), "=r"(r[2]), "=r"(r[3]) : "r"(addr));
}
__device__ __forceinline__ void mma16816(float* d, const uint32_t* a,
                                         const uint32_t* b) {
    asm volatile(
        "mma.sync.aligned.m16n8k16.row.col.f32.bf16.bf16.f32 "
        "{%0,%1,%2,%3}, {%4,%5,%6,%7}, {%8,%9}, {%0,%1,%2,%3};"
        : "+f"(d[0]), "+f"(d[1]), "+f"(d[2]), "+f"(d[3])
        : "r"(a[0]), "r"(a[1]), "r"(a[2]), "r"(a[3]), "r"(b[0]), "r"(b[1]));
}
#define CPA16(dst, src) \
    asm volatile("cp.async.cg.shared.global [%0], [%1], 16;" \
                 :: "r"(dst), "l"(src) : "memory")
#define CP_COMMIT() asm volatile("cp.async.commit_group;" ::: "memory")

__device__ __forceinline__ void split2(float v0, float v1,
                                       uint32_t& h, uint32_t& l) {
    __nv_bfloat16 h0 = __float2bfloat16_rn(v0), h1 = __float2bfloat16_rn(v1);
    __nv_bfloat162 hh(h0, h1);
    __nv_bfloat162 ll(__float2bfloat16_rn(v0 - __bfloat162float(h0)),
                      __float2bfloat16_rn(v1 - __bfloat162float(h1)));
    h = *reinterpret_cast<uint32_t*>(&hh);
    l = *reinterpret_cast<uint32_t*>(&ll);
}

// ---------------------------------------------------------------- split
__global__ void __launch_bounds__(256)
split_arr(const float* __restrict__ in, __nv_bfloat16* __restrict__ oh,
          __nv_bfloat16* __restrict__ ol, long n)
{
    long i = ((long)blockIdx.x * 256 + threadIdx.x) * 4;
    if (i >= n) return;
    float4 v = *reinterpret_cast<const float4*>(in + i);
    uint2 h, l;
    split2(v.x, v.y, h.x, l.x);
    split2(v.z, v.w, h.y, l.y);
    *reinterpret_cast<uint2*>(oh + i) = h;
    *reinterpret_cast<uint2*>(ol + i) = l;
}

// ---------------------------------------------------------------- mainloop
// 256 thr, 8 warps (2m x 4n), warp tile 64x32, CTA tile 128x128, K-chunk 64.
// gA*/gB* already offset to (row0, col0). acc[64] per thread.
__device__ __forceinline__ void gemm_mainloop(
    const __nv_bfloat16* __restrict__ gAh, const __nv_bfloat16* __restrict__ gAl,
    const __nv_bfloat16* __restrict__ gBh, const __nv_bfloat16* __restrict__ gBl,
    int lda, int ldb, int K, uint32_t abase, float* acc)
{
    const int tid = threadIdx.x, lane = tid & 31, wid = tid >> 5;

    // loader: row r0 = tid>>1 (0..127), seg group (tid&1)*4 (4 x 16B each)
    const int r0 = tid >> 1, sg = (tid & 1) * 4;
    uint32_t sw[4];
#pragma unroll
    for (int q = 0; q < 4; q++)
        sw[q] = SWZ((uint32_t)r0 * 128 + (sg + q) * 16);
    const __nv_bfloat16* pAh = gAh + (long)r0 * lda + sg * 8;
    const __nv_bfloat16* pAl = gAl + (long)r0 * lda + sg * 8;
    const __nv_bfloat16* pBh = gBh + (long)r0 * ldb + sg * 8;
    const __nv_bfloat16* pBl = gBl + (long)r0 * ldb + sg * 8;

    // fragment constants
    const int mw = (wid >> 2) * 64, nw = (wid & 3) * 32;
    uint32_t a_row[4], a_swz[4];
#pragma unroll
    for (int i = 0; i < 4; i++) {
        const uint32_t rb = (uint32_t)(mw + 16 * i + (lane & 15)) * 128;
        a_row[i] = rb; a_swz[i] = (rb >> 3) & 0x70;
    }
    const uint32_t a_kl = (uint32_t)((lane >> 4) << 4);
    uint32_t b_row[2], b_swz[2];
#pragma unroll
    for (int p = 0; p < 2; p++) {
        const uint32_t rb =
            (uint32_t)(nw + 16 * p + (lane & 7) + ((lane & 16) >> 1)) * 128;
        b_row[p] = rb; b_swz[p] = (rb >> 3) & 0x70;
    }
    const uint32_t b_kl = (uint32_t)((lane & 8) << 1);

    const int nch = K >> 6;

#define ISSUE(ch) do {                                                        \
        const uint32_t _sb = abase + (uint32_t)((ch) % NSTG) * STAGE;         \
        const long _k = (long)(ch) * 64;                                      \
        _Pragma("unroll")                                                     \
        for (int q = 0; q < 4; q++) {                                         \
            CPA16(_sb + OFF_AH + sw[q], pAh + _k + q * 8);                    \
            CPA16(_sb + OFF_AL + sw[q], pAl + _k + q * 8);                    \
            CPA16(_sb + OFF_BH + sw[q], pBh + _k + q * 8);                    \
            CPA16(_sb + OFF_BL + sw[q], pBl + _k + q * 8);                    \
        }                                                                     \
        CP_COMMIT();                                                          \
    } while (0)

    ISSUE(0);
    ISSUE(1);

    for (int ch = 0; ch < nch; ch++) {
        if (ch + 1 < nch)
            asm volatile("cp.async.wait_group 1;" ::: "memory");
        else
            asm volatile("cp.async.wait_group 0;" ::: "memory");
        __syncthreads();
        if (ch + 2 < nch) ISSUE(ch + 2);

        const uint32_t sb = abase + (uint32_t)(ch % NSTG) * STAGE;
#pragma unroll
        for (int ks = 0; ks < 4; ks++) {
            const uint32_t KB = ks * 32;
            uint32_t af[4][4], bh[8], bl[8];
#pragma unroll
            for (int i = 0; i < 4; i++)                   // A hi (64 rows)
                ldsm4(af[i], sb + OFF_AH + a_row[i] + ((KB + a_kl) ^ a_swz[i]));
#pragma unroll
            for (int p = 0; p < 2; p++) {                 // B hi + lo (32 rows)
                const uint32_t ko = KB + b_kl;
                ldsm4(&bh[4 * p], sb + OFF_BH + b_row[p] + (ko ^ b_swz[p]));
                ldsm4(&bl[4 * p], sb + OFF_BL + b_row[p] + (ko ^ b_swz[p]));
            }
#pragma unroll
            for (int i = 0; i < 4; i++)
#pragma unroll
                for (int j = 0; j < 4; j++)
                    mma16816(acc + (i * 4 + j) * 4, af[i], &bh[j * 2]);  // hi*hi
#pragma unroll
            for (int i = 0; i < 4; i++)
#pragma unroll
                for (int j = 0; j < 4; j++)
                    mma16816(acc + (i * 4 + j) * 4, af[i], &bl[j * 2]);  // hi*lo
#pragma unroll
            for (int i = 0; i < 4; i++)                   // A lo (reuse regs)
                ldsm4(af[i], sb + OFF_AL + a_row[i] + ((KB + a_kl) ^ a_swz[i]));
#pragma unroll
            for (int i = 0; i < 4; i++)
#pragma unroll
                for (int j = 0; j < 4; j++)
                    mma16816(acc + (i * 4 + j) * 4, af[i], &bh[j * 2]);  // lo*hi
        }
    }
#undef ISSUE
}

// ---------------------------------------------------------------- fused QKV
// grid (D/128, NB*S/128, 3): z=0 -> Q, z=1 -> K (row-major bf16 pairs),
// z=2 -> VT (per-batch transposed bf16 pairs, ld = S).
__global__ void __launch_bounds__(256, 1)
mma_qkv(const float* __restrict__ bq, const float* __restrict__ bk,
        const float* __restrict__ bv)
{
    const int z = blockIdx.z;
    const long row0 = (long)blockIdx.y * 128, col0 = (long)blockIdx.x * 128;

    extern __shared__ char smem_raw[];
    const uint32_t rawb  = smem_u32(smem_raw);
    const uint32_t abase = (rawb + 1023) & ~1023u;
    char* smem = smem_raw + (abase - rawb);

    const __nv_bfloat16* Wh = &g_bf[z == 0 ? OWQH : z == 1 ? OWKH : OWVH];
    const __nv_bfloat16* Wl = &g_bf[z == 0 ? OWQL : z == 1 ? OWKL : OWVL];
    const float* bias = z == 0 ? bq : z == 1 ? bk : bv;

    float acc[64];
#pragma unroll
    for (int i = 0; i < 64; i++) acc[i] = 0.f;

    gemm_mainloop(&g_bf[OXH] + row0 * D, &g_bf[OXL] + row0 * D,
                  Wh + col0 * D, Wl + col0 * D, D, D, D, abase, acc);

    const int tid = threadIdx.x, lane = tid & 31, wid = tid >> 5;
    const int mw = (wid >> 2) * 64, nw = (wid & 3) * 32;
    const int qr = lane >> 2, qc = lane & 3;

    if (z < 2) {
        __nv_bfloat16* Ch = &g_bf[z == 0 ? OQH : OKH];
        __nv_bfloat16* Cl = &g_bf[z == 0 ? OQL : OKL];
#pragma unroll
        for (int i = 0; i < 4; i++)
#pragma unroll
            for (int j = 0; j < 4; j++) {
                const float* d = acc + (i * 4 + j) * 4;
#pragma unroll
                for (int h = 0; h < 2; h++) {
                    const long r = row0 + mw + 16 * i + qr + 8 * h;
                    const long c = col0 + nw + 8 * j + 2 * qc;
                    float v0 = d[2 * h] + bias[c], v1 = d[2 * h + 1] + bias[c + 1];
                    uint32_t hh, ll;
                    split2(v0, v1, hh, ll);
                    *reinterpret_cast<uint32_t*>(&Ch[r * D + c]) = hh;
                    *reinterpret_cast<uint32_t*>(&Cl[r * D + c]) = ll;
                }
            }
    } else {
        // VT: stage transposed tile in smem, coalesced stores. batch = row0/S.
        const long b = row0 >> 11, rloc = row0 & (S - 1);
        __nv_bfloat16* Ch = &g_bf[OVTH] + b * SD;
        __nv_bfloat16* Cl = &g_bf[OVTL] + b * SD;
        __syncthreads();
        __nv_bfloat16* sh = reinterpret_cast<__nv_bfloat16*>(smem);
        __nv_bfloat16* sl = sh + 128 * 136;
#pragma unroll
        for (int i = 0; i < 4; i++)
#pragma unroll
            for (int j = 0; j < 4; j++) {
                const float* d = acc + (i * 4 + j) * 4;
#pragma unroll
                for (int h = 0; h < 2; h++) {
                    const int rl = mw + 16 * i + qr + 8 * h;
                    const int cl = nw + 8 * j + 2 * qc;
                    float v0 = d[2 * h] + bias[col0 + cl];
                    float v1 = d[2 * h + 1] + bias[col0 + cl + 1];
                    __nv_bfloat16 h0 = __float2bfloat16_rn(v0);
                    __nv_bfloat16 h1 = __float2bfloat16_rn(v1);
                    sh[cl * 136 + rl]       = h0;
                    sh[(cl + 1) * 136 + rl] = h1;
                    sl[cl * 136 + rl] =
                        __float2bfloat16_rn(v0 - __bfloat162float(h0));
                    sl[(cl + 1) * 136 + rl] =
                        __float2bfloat16_rn(v1 - __bfloat162float(h1));
                }
            }
        __syncthreads();
        const int c = tid >> 1, seg = tid & 1;     // 128 cols x 2 segs of 128B
        const __nv_bfloat16* srh = sh + c * 136 + seg * 64;
        const __nv_bfloat16* srl = sl + c * 136 + seg * 64;
        __nv_bfloat16* dsh = Ch + (col0 + c) * (long)S + rloc + seg * 64;
        __nv_bfloat16* dsl = Cl + (col0 + c) * (long)S + rloc + seg * 64;
#pragma unroll
        for (int q = 0; q < 8; q++) {
            *reinterpret_cast<uint4*>(dsh + q * 8) =
                *reinterpret_cast<const uint4*>(srh + q * 8);
            *reinterpret_cast<uint4*>(dsl + q * 8) =
                *reinterpret_cast<const uint4*>(srl + q * 8);
        }
    }
}

// ---------------------------------------------------------------- generic GEMM
// fp32 out: Cf[r*ldc + c] = scale * A@B^T. Batched by blockIdx.z.
__global__ void __launch_bounds__(256, 1)
mma_gemm(const __nv_bfloat16* __restrict__ Ah, const __nv_bfloat16* __restrict__ Al,
         const __nv_bfloat16* __restrict__ Bh, const __nv_bfloat16* __restrict__ Bl,
         float* __restrict__ Cf, int K, int lda, int ldb, int ldc,
         long sA, long sB, long sC, float scale)
{
    const long zb = blockIdx.z;
    const long row0 = (long)blockIdx.y * 128, col0 = (long)blockIdx.x * 128;

    extern __shared__ char smem_raw[];
    const uint32_t rawb  = smem_u32(smem_raw);
    const uint32_t abase = (rawb + 1023) & ~1023u;

    float acc[64];
#pragma unroll
    for (int i = 0; i < 64; i++) acc[i] = 0.f;

    gemm_mainloop(Ah + sA * zb + row0 * (long)lda, Al + sA * zb + row0 * (long)lda,
                  Bh + sB * zb + col0 * (long)ldb, Bl + sB * zb + col0 * (long)ldb,
                  lda, ldb, K, abase, acc);

    float* Cp = Cf + sC * zb;
    const int tid = threadIdx.x, lane = tid & 31, wid = tid >> 5;
    const int mw = (wid >> 2) * 64, nw = (wid & 3) * 32;
    const int qr = lane >> 2, qc = lane & 3;
#pragma unroll
    for (int i = 0; i < 4; i++)
#pragma unroll
        for (int j = 0; j < 4; j++) {
            const float* d = acc + (i * 4 + j) * 4;
#pragma unroll
            for (int h = 0; h < 2; h++) {
                const long r = row0 + mw + 16 * i + qr + 8 * h;
                const long c = col0 + nw + 8 * j + 2 * qc;
                *reinterpret_cast<float2*>(&Cp[r * (long)ldc + c]) =
                    make_float2(d[2 * h] * scale, d[2 * h + 1] * scale);
            }
        }
}

// ---------------------------------------------------------------- softmax
__global__ void __launch_bounds__(256)
softmax_rows(const float* __restrict__ sc, __nv_bfloat16* __restrict__ ph,
             __nv_bfloat16* __restrict__ pl)
{
    const long ro = (long)blockIdx.x * 2048;
    const float* p = sc + ro;
    __shared__ float red[256];
    const int t = threadIdx.x;

    float v[8];
    float m = -3.4e38f;
#pragma unroll
    for (int i = 0; i < 8; i++) { v[i] = p[t + (i << 8)]; m = fmaxf(m, v[i]); }
    red[t] = m;
    __syncthreads();
    for (int s = 128; s > 0; s >>= 1) {
        if (t < s) red[t] = fmaxf(red[t], red[t + s]);
        __syncthreads();
    }
    m = red[0];
    __syncthreads();

    float sum = 0.f;
#pragma unroll
    for (int i = 0; i < 8; i++) { v[i] = __expf(v[i] - m); sum += v[i]; }
    red[t] = sum;
    __syncthreads();
    for (int s = 128; s > 0; s >>= 1) {
        if (t < s) red[t] += red[t + s];
        __syncthreads();
    }
    const float inv = 1.f / red[0];
#pragma unroll
    for (int i = 0; i < 8; i++) {
        float pv = v[i] * inv;
        __nv_bfloat16 h = __float2bfloat16_rn(pv);
        ph[ro + t + (i << 8)] = h;
        pl[ro + t + (i << 8)] = __float2bfloat16_rn(pv - __bfloat162float(h));
    }
}

// ---------------------------------------------------------------- launch
extern "C" void kernel_launch(void* const* d_in, const int* in_sizes, int n_in,
                              void* d_out, int out_size)
{
    const float* x  = (const float*)d_in[0];
    const float* Wq = (const float*)d_in[1];
    const float* bq = (const float*)d_in[2];
    const float* Wk = (const float*)d_in[3];
    const float* bk = (const float*)d_in[4];
    const float* Wv = (const float*)d_in[5];
    const float* bv = (const float*)d_in[6];
    float* out = (float*)d_out;

    __nv_bfloat16* bf; float* scp;
    cudaGetSymbolAddress((void**)&bf, g_bf);
    cudaGetSymbolAddress((void**)&scp, g_sc);

    cudaFuncSetAttribute(mma_qkv, cudaFuncAttributeMaxDynamicSharedMemorySize,
                         SMEM_DYN);
    cudaFuncSetAttribute(mma_gemm, cudaFuncAttributeMaxDynamicSharedMemorySize,
                         SMEM_DYN);
    dim3 thr(256);

    split_arr<<<(int)(NX / 1024), 256>>>(x,  bf + OXH,  bf + OXL,  NX);
    split_arr<<<(int)(NW / 1024), 256>>>(Wq, bf + OWQH, bf + OWQL, NW);
    split_arr<<<(int)(NW / 1024), 256>>>(Wk, bf + OWKH, bf + OWKL, NW);
    split_arr<<<(int)(NW / 1024), 256>>>(Wv, bf + OWVH, bf + OWVL, NW);

    // fused Q/K/VT projections
    dim3 g_qkv(D / 128, (NB * S) / 128, 3);
    mma_qkv<<<g_qkv, thr, SMEM_DYN>>>(bq, bk, bv);

    // Sc = Q@K^T / 32 (fp32), batched
    dim3 g_sc(S / 128, S / 128, NB);
    mma_gemm<<<g_sc, thr, SMEM_DYN>>>(bf+OQH, bf+OQL, bf+OKH, bf+OKL,
                                      scp, D, D, D, S, SD, SD, SSZ, 0.03125f);

    softmax_rows<<<NB * S, 256>>>(scp, bf + OPH, bf + OPL);

    // O = P@VT^T (fp32), batched, K = S
    dim3 g_o(D / 128, S / 128, NB);
    mma_gemm<<<g_o, thr, SMEM_DYN>>>(bf+OPH, bf+OPL, bf+OVTH, bf+OVTL,
                                     out, S, S, S, D, SSZ, SD, SD, 1.f);
}

// round 8
// speedup vs baseline: 1.1762x; 1.1762x over previous
#include <cuda_runtime.h>
#include <cuda_bf16.h>
#include <cstdint>

// ============================================================================
// SelfAttention, mma.sync bf16x3-split, cp.async 4-stage pipeline.
// R8: CTA tile 128x64, warp tile 32x16 (16 warps, 512 thr), K-chunk 32,
// packed [hi|lo] 128B smem rows, <=64 regs/thread -> 2 CTAs/SM (8 warps/SMSP)
// for stall hiding. Same numerics as R4 (rel_err 1.8e-5).
// ============================================================================

constexpr int S = 2048, D = 1024, NB = 4;
constexpr long SD  = (long)S * D;
constexpr long SSZ = (long)S * S;
constexpr long NX = (long)NB * S * D;
constexpr long NW = (long)D * D;
constexpr long NP = (long)NB * S * S;

constexpr long OXH = 0,        OXL = NX;
constexpr long OWQH = 2*NX,    OWQL = OWQH+NW, OWKH = OWQH+2*NW, OWKL = OWQH+3*NW,
               OWVH = OWQH+4*NW, OWVL = OWQH+5*NW;
constexpr long OQH = 2*NX+6*NW, OQL = OQH+NX, OKH = OQH+2*NX, OKL = OQH+3*NX,
               OVTH = OQH+4*NX, OVTL = OQH+5*NX;
constexpr long OPH = OQH+6*NX,  OPL = OPH+NP;
constexpr long NBF = OPL + NP;

__device__ __align__(128) __nv_bfloat16 g_bf[NBF];
__device__ float g_sc[NP];

// stage: A 128 rows x 128B ([k0..31 hi | k0..31 lo]) = 16KB, B 64 x 128B = 8KB
constexpr int STAGE = 24 * 1024;
constexpr int OFF_B = 16384;
constexpr int NSTG  = 4;
constexpr int SMEM_DYN = NSTG * STAGE + 1024;   // 99,328 -> 2 CTAs/SM

#define SWZ(o) ((o) ^ (((o) >> 3) & 0x70))

// ---------------------------------------------------------------- helpers
__device__ __forceinline__ uint32_t smem_u32(const void* p) {
    uint32_t a;
    asm("{ .reg .u64 t; cvta.to.shared.u64 t, %1; cvt.u32.u64 %0, t; }"
        : "=r"(a) : "l"(p));
    return a;
}
__device__ __forceinline__ void ldsm4(uint32_t* r, uint32_t addr) {
    asm volatile("ldmatrix.sync.aligned.m8n8.x4.shared.b16 {%0,%1,%2,%3}, [%4];"
                 : "=r"(r[0]), "=r"(r[1]), "=r"(r[2]), "=r"(r[3]) : "r"(addr));
}
__device__ __forceinline__ void mma16816(float* d, const uint32_t* a,
                                         const uint32_t* b) {
    asm volatile(
        "mma.sync.aligned.m16n8k16.row.col.f32.bf16.bf16.f32 "
        "{%0,%1,%2,%3}, {%4,%5,%6,%7}, {%8,%9}, {%0,%1,%2,%3};"
        : "+f"(d[0]), "+f"(d[1]), "+f"(d[2]), "+f"(d[3])
        : "r"(a[0]), "r"(a[1]), "r"(a[2]), "r"(a[3]), "r"(b[0]), "r"(b[1]));
}
#define CPA16(dst, src) \
    asm volatile("cp.async.cg.shared.global [%0], [%1], 16;" \
                 :: "r"(dst), "l"(src) : "memory")
#define CP_COMMIT() asm volatile("cp.async.commit_group;" ::: "memory")
#define WG(n) asm volatile("cp.async.wait_group %0;" :: "n"(n) : "memory")

__device__ __forceinline__ void split2(float v0, float v1,
                                       uint32_t& h, uint32_t& l) {
    __nv_bfloat16 h0 = __float2bfloat16_rn(v0), h1 = __float2bfloat16_rn(v1);
    __nv_bfloat162 hh(h0, h1);
    __nv_bfloat162 ll(__float2bfloat16_rn(v0 - __bfloat162float(h0)),
                      __float2bfloat16_rn(v1 - __bfloat162float(h1)));
    h = *reinterpret_cast<uint32_t*>(&hh);
    l = *reinterpret_cast<uint32_t*>(&ll);
}

// ---------------------------------------------------------------- split
__global__ void __launch_bounds__(256)
split_arr(const float* __restrict__ in, __nv_bfloat16* __restrict__ oh,
          __nv_bfloat16* __restrict__ ol, long n)
{
    long i = ((long)blockIdx.x * 256 + threadIdx.x) * 4;
    if (i >= n) return;
    float4 v = *reinterpret_cast<const float4*>(in + i);
    uint2 h, l;
    split2(v.x, v.y, h.x, l.x);
    split2(v.z, v.w, h.y, l.y);
    *reinterpret_cast<uint2*>(oh + i) = h;
    *reinterpret_cast<uint2*>(ol + i) = l;
}

// ---------------------------------------------------------------- mainloop
// 512 thr, 16 warps (4m x 4n), warp 32x16, CTA 128(m) x 64(n), K-chunk 32.
// gA*/gB* pre-offset to (row0, col0). acc[16].
__device__ __forceinline__ void gemm_mainloop(
    const __nv_bfloat16* __restrict__ gAh, const __nv_bfloat16* __restrict__ gAl,
    const __nv_bfloat16* __restrict__ gBh, const __nv_bfloat16* __restrict__ gBl,
    int lda, int ldb, int K, uint32_t abase, float* acc)
{
    const int tid = threadIdx.x, lane = tid & 31, wid = tid >> 5;

    // loaders: A: thread -> row ra, 16B unit qa (hi) + same unit in lo half.
    const int ra = tid >> 2, qa = tid & 3;
    const uint32_t swA0 = SWZ((uint32_t)ra * 128 + qa * 16);
    const uint32_t swA1 = SWZ((uint32_t)ra * 128 + 64 + qa * 16);
    const __nv_bfloat16* pAh = gAh + (long)ra * lda + qa * 8;
    const __nv_bfloat16* pAl = gAl + (long)ra * lda + qa * 8;
    // B: thread -> row rb, unit ub (0-3 hi from Bh, 4-7 lo from Bl)
    const int rb = tid >> 3, ub = tid & 7;
    const uint32_t swB = OFF_B + SWZ((uint32_t)rb * 128 + ub * 16);
    const __nv_bfloat16* pB =
        (ub < 4 ? gBh : gBl) + (long)rb * ldb + (ub & 3) * 8;

    // fragment constants
    const int mw = (wid >> 2) * 32, nw = (wid & 3) * 16;
    uint32_t a_row[2], a_swz[2];
#pragma unroll
    for (int i = 0; i < 2; i++) {
        const uint32_t rbb = (uint32_t)(mw + 16 * i + (lane & 15)) * 128;
        a_row[i] = rbb; a_swz[i] = (rbb >> 3) & 0x70;
    }
    const uint32_t a_kl = (uint32_t)((lane >> 4) << 4);
    const uint32_t b_rw =
        (uint32_t)(nw + (lane & 7) + ((lane & 16) >> 1)) * 128;
    const uint32_t b_sz = (b_rw >> 3) & 0x70;
    const uint32_t b_kl = (uint32_t)((lane & 8) << 1);

    const int nch = K >> 5;

#define ISSUE(ch) do {                                                        \
        const uint32_t _sb = abase + (uint32_t)((ch) & 3) * STAGE;            \
        const long _k = (long)(ch) * 32;                                      \
        CPA16(_sb + swA0, pAh + _k);                                          \
        CPA16(_sb + swA1, pAl + _k);                                          \
        CPA16(_sb + swB,  pB  + _k);                                          \
        CP_COMMIT();                                                          \
    } while (0)

    ISSUE(0); ISSUE(1); ISSUE(2);

    for (int ch = 0; ch < nch; ch++) {
        __syncthreads();
        if (ch + 3 < nch) { ISSUE(ch + 3); WG(3); }
        else {
            const int rem = nch - 1 - ch;
            if (rem == 2) WG(2); else if (rem == 1) WG(1); else WG(0);
        }
        __syncthreads();

        const uint32_t sb = abase + (uint32_t)(ch & 3) * STAGE;
#pragma unroll
        for (int ks = 0; ks < 2; ks++) {
            const uint32_t kb = ks * 32;
            uint32_t af[2][4], bh[4], bl[4];
#pragma unroll
            for (int i = 0; i < 2; i++)
                ldsm4(af[i], sb + a_row[i] + ((kb + a_kl) ^ a_swz[i]));
            ldsm4(bh, sb + OFF_B + b_rw + ((kb + b_kl) ^ b_sz));
            ldsm4(bl, sb + OFF_B + b_rw + ((kb + 64 + b_kl) ^ b_sz));
#pragma unroll
            for (int i = 0; i < 2; i++)
#pragma unroll
                for (int j = 0; j < 2; j++)
                    mma16816(acc + (i * 2 + j) * 4, af[i], &bh[j * 2]); // hi*hi
#pragma unroll
            for (int i = 0; i < 2; i++)
#pragma unroll
                for (int j = 0; j < 2; j++)
                    mma16816(acc + (i * 2 + j) * 4, af[i], &bl[j * 2]); // hi*lo
#pragma unroll
            for (int i = 0; i < 2; i++)   // reload A as lo
                ldsm4(af[i], sb + a_row[i] + ((kb + 64 + a_kl) ^ a_swz[i]));
#pragma unroll
            for (int i = 0; i < 2; i++)
#pragma unroll
                for (int j = 0; j < 2; j++)
                    mma16816(acc + (i * 2 + j) * 4, af[i], &bh[j * 2]); // lo*hi
        }
    }
#undef ISSUE
}

// ---------------------------------------------------------------- fused QKV
// grid (D/64, NB*S/128, 3): z=0 Q, z=1 K (row-major bf16 pairs),
// z=2 VT (per-batch transposed pairs, ld = S).
__global__ void __launch_bounds__(512, 2)
mma_qkv(const float* __restrict__ bq, const float* __restrict__ bk,
        const float* __restrict__ bv)
{
    const int z = blockIdx.z;
    const long row0 = (long)blockIdx.y * 128, col0 = (long)blockIdx.x * 64;

    extern __shared__ char smem_raw[];
    const uint32_t rawb  = smem_u32(smem_raw);
    const uint32_t abase = (rawb + 1023) & ~1023u;
    char* smem = smem_raw + (abase - rawb);

    const __nv_bfloat16* Wh = &g_bf[z == 0 ? OWQH : z == 1 ? OWKH : OWVH];
    const __nv_bfloat16* Wl = &g_bf[z == 0 ? OWQL : z == 1 ? OWKL : OWVL];
    const float* bias = z == 0 ? bq : z == 1 ? bk : bv;

    float acc[16];
#pragma unroll
    for (int i = 0; i < 16; i++) acc[i] = 0.f;

    gemm_mainloop(&g_bf[OXH] + row0 * D, &g_bf[OXL] + row0 * D,
                  Wh + col0 * D, Wl + col0 * D, D, D, D, abase, acc);

    const int tid = threadIdx.x, lane = tid & 31, wid = tid >> 5;
    const int mw = (wid >> 2) * 32, nw = (wid & 3) * 16;
    const int qr = lane >> 2, qc = lane & 3;

    if (z < 2) {
        __nv_bfloat16* Ch = &g_bf[z == 0 ? OQH : OKH];
        __nv_bfloat16* Cl = &g_bf[z == 0 ? OQL : OKL];
#pragma unroll
        for (int i = 0; i < 2; i++)
#pragma unroll
            for (int j = 0; j < 2; j++) {
                const float* d = acc + (i * 2 + j) * 4;
#pragma unroll
                for (int h = 0; h < 2; h++) {
                    const long r = row0 + mw + 16 * i + qr + 8 * h;
                    const long c = col0 + nw + 8 * j + 2 * qc;
                    float v0 = d[2 * h] + bias[c], v1 = d[2 * h + 1] + bias[c + 1];
                    uint32_t hh, ll;
                    split2(v0, v1, hh, ll);
                    *reinterpret_cast<uint32_t*>(&Ch[r * D + c]) = hh;
                    *reinterpret_cast<uint32_t*>(&Cl[r * D + c]) = ll;
                }
            }
    } else {
        // VT: stage transposed 64x128 tile in smem, coalesced 16B stores.
        const long b = row0 >> 11, rloc = row0 & (S - 1);
        __nv_bfloat16* Ch = &g_bf[OVTH] + b * SD;
        __nv_bfloat16* Cl = &g_bf[OVTL] + b * SD;
        __syncthreads();
        __nv_bfloat16* sh = reinterpret_cast<__nv_bfloat16*>(smem);
        __nv_bfloat16* sl = sh + 64 * 136;
#pragma unroll
        for (int i = 0; i < 2; i++)
#pragma unroll
            for (int j = 0; j < 2; j++) {
                const float* d = acc + (i * 2 + j) * 4;
#pragma unroll
                for (int h = 0; h < 2; h++) {
                    const int rl = mw + 16 * i + qr + 8 * h;
                    const int cl = nw + 8 * j + 2 * qc;
                    float v0 = d[2 * h] + bias[col0 + cl];
                    float v1 = d[2 * h + 1] + bias[col0 + cl + 1];
                    __nv_bfloat16 h0 = __float2bfloat16_rn(v0);
                    __nv_bfloat16 h1 = __float2bfloat16_rn(v1);
                    sh[cl * 136 + rl]       = h0;
                    sh[(cl + 1) * 136 + rl] = h1;
                    sl[cl * 136 + rl] =
                        __float2bfloat16_rn(v0 - __bfloat162float(h0));
                    sl[(cl + 1) * 136 + rl] =
                        __float2bfloat16_rn(v1 - __bfloat162float(h1));
                }
            }
        __syncthreads();
        const int c = tid >> 3, seg = tid & 7;   // 64 cols x 8 segs of 16B
        const __nv_bfloat16* srh = sh + c * 136 + seg * 8;
        const __nv_bfloat16* srl = sl + c * 136 + seg * 8;
        __nv_bfloat16* dsh = Ch + (col0 + c) * (long)S + rloc + seg * 8;
        __nv_bfloat16* dsl = Cl + (col0 + c) * (long)S + rloc + seg * 8;
        *reinterpret_cast<uint4*>(dsh) = *reinterpret_cast<const uint4*>(srh);
        *reinterpret_cast<uint4*>(dsl) = *reinterpret_cast<const uint4*>(srl);
        // remaining 64B of each 128-elem row
#pragma unroll
        for (int q = 1; q < 2; q++) {
            *reinterpret_cast<uint4*>(dsh + 64) =
                *reinterpret_cast<const uint4*>(srh + 64);
            *reinterpret_cast<uint4*>(dsl + 64) =
                *reinterpret_cast<const uint4*>(srl + 64);
        }
    }
}

// ---------------------------------------------------------------- generic GEMM
// fp32 out: Cf[r*ldc + c] = scale * A@B^T. Batched by blockIdx.z.
__global__ void __launch_bounds__(512, 2)
mma_gemm(const __nv_bfloat16* __restrict__ Ah, const __nv_bfloat16* __restrict__ Al,
         const __nv_bfloat16* __restrict__ Bh, const __nv_bfloat16* __restrict__ Bl,
         float* __restrict__ Cf, int K, int lda, int ldb, int ldc,
         long sA, long sB, long sC, float scale)
{
    const long zb = blockIdx.z;
    const long row0 = (long)blockIdx.y * 128, col0 = (long)blockIdx.x * 64;

    extern __shared__ char smem_raw[];
    const uint32_t rawb  = smem_u32(smem_raw);
    const uint32_t abase = (rawb + 1023) & ~1023u;

    float acc[16];
#pragma unroll
    for (int i = 0; i < 16; i++) acc[i] = 0.f;

    gemm_mainloop(Ah + sA * zb + row0 * (long)lda, Al + sA * zb + row0 * (long)lda,
                  Bh + sB * zb + col0 * (long)ldb, Bl + sB * zb + col0 * (long)ldb,
                  lda, ldb, K, abase, acc);

    float* Cp = Cf + sC * zb;
    const int tid = threadIdx.x, lane = tid & 31, wid = tid >> 5;
    const int mw = (wid >> 2) * 32, nw = (wid & 3) * 16;
    const int qr = lane >> 2, qc = lane & 3;
#pragma unroll
    for (int i = 0; i < 2; i++)
#pragma unroll
        for (int j = 0; j < 2; j++) {
            const float* d = acc + (i * 2 + j) * 4;
#pragma unroll
            for (int h = 0; h < 2; h++) {
                const long r = row0 + mw + 16 * i + qr + 8 * h;
                const long c = col0 + nw + 8 * j + 2 * qc;
                *reinterpret_cast<float2*>(&Cp[r * (long)ldc + c]) =
                    make_float2(d[2 * h] * scale, d[2 * h + 1] * scale);
            }
        }
}

// ---------------------------------------------------------------- softmax
__global__ void __launch_bounds__(256)
softmax_rows(const float* __restrict__ sc, __nv_bfloat16* __restrict__ ph,
             __nv_bfloat16* __restrict__ pl)
{
    const long ro = (long)blockIdx.x * 2048;
    const float* p = sc + ro;
    __shared__ float red[256];
    const int t = threadIdx.x;

    float v[8];
    float m = -3.4e38f;
#pragma unroll
    for (int i = 0; i < 8; i++) { v[i] = p[t + (i << 8)]; m = fmaxf(m, v[i]); }
    red[t] = m;
    __syncthreads();
    for (int s = 128; s > 0; s >>= 1) {
        if (t < s) red[t] = fmaxf(red[t], red[t + s]);
        __syncthreads();
    }
    m = red[0];
    __syncthreads();

    float sum = 0.f;
#pragma unroll
    for (int i = 0; i < 8; i++) { v[i] = __expf(v[i] - m); sum += v[i]; }
    red[t] = sum;
    __syncthreads();
    for (int s = 128; s > 0; s >>= 1) {
        if (t < s) red[t] += red[t + s];
        __syncthreads();
    }
    const float inv = 1.f / red[0];
#pragma unroll
    for (int i = 0; i < 8; i++) {
        float pv = v[i] * inv;
        __nv_bfloat16 h = __float2bfloat16_rn(pv);
        ph[ro + t + (i << 8)] = h;
        pl[ro + t + (i << 8)] = __float2bfloat16_rn(pv - __bfloat162float(h));
    }
}

// ---------------------------------------------------------------- launch
extern "C" void kernel_launch(void* const* d_in, const int* in_sizes, int n_in,
                              void* d_out, int out_size)
{
    const float* x  = (const float*)d_in[0];
    const float* Wq = (const float*)d_in[1];
    const float* bq = (const float*)d_in[2];
    const float* Wk = (const float*)d_in[3];
    const float* bk = (const float*)d_in[4];
    const float* Wv = (const float*)d_in[5];
    const float* bv = (const float*)d_in[6];
    float* out = (float*)d_out;

    __nv_bfloat16* bf; float* scp;
    cudaGetSymbolAddress((void**)&bf, g_bf);
    cudaGetSymbolAddress((void**)&scp, g_sc);

    cudaFuncSetAttribute(mma_qkv, cudaFuncAttributeMaxDynamicSharedMemorySize,
                         SMEM_DYN);
    cudaFuncSetAttribute(mma_gemm, cudaFuncAttributeMaxDynamicSharedMemorySize,
                         SMEM_DYN);
    dim3 thr(512);

    split_arr<<<(int)(NX / 1024), 256>>>(x,  bf + OXH,  bf + OXL,  NX);
    split_arr<<<(int)(NW / 1024), 256>>>(Wq, bf + OWQH, bf + OWQL, NW);
    split_arr<<<(int)(NW / 1024), 256>>>(Wk, bf + OWKH, bf + OWKL, NW);
    split_arr<<<(int)(NW / 1024), 256>>>(Wv, bf + OWVH, bf + OWVL, NW);

    // fused Q/K/VT projections
    dim3 g_qkv(D / 64, (NB * S) / 128, 3);
    mma_qkv<<<g_qkv, thr, SMEM_DYN>>>(bq, bk, bv);

    // Sc = Q@K^T / 32 (fp32), batched
    dim3 g_sc(S / 64, S / 128, NB);
    mma_gemm<<<g_sc, thr, SMEM_DYN>>>(bf+OQH, bf+OQL, bf+OKH, bf+OKL,
                                      scp, D, D, D, S, SD, SD, SSZ, 0.03125f);

    softmax_rows<<<NB * S, 256>>>(scp, bf + OPH, bf + OPL);

    // O = P@VT^T (fp32), batched, K = S
    dim3 g_o(D / 64, S / 128, NB);
    mma_gemm<<<g_o, thr, SMEM_DYN>>>(bf+OPH, bf+OPL, bf+OVTH, bf+OVTL,
                                     out, S, S, S, D, SSZ, SD, SD, 1.f);
}

// round 9
// speedup vs baseline: 1.2751x; 1.0841x over previous
#include <cuda_runtime.h>
#include <cuda_bf16.h>
#include <cstdint>

// ============================================================================
// SelfAttention, mma.sync bf16x3-split, cp.async 3-stage pipelined GEMMs.
// R9 = R4/R6 proven geometry (512 thr, CTA 128x128, warp 32x32, K-chunk 64)
// + fused QKV launch (grid.z: 0=Q, 1=K, 2=VT) + shuffle softmax.
// Launch order puts the score GEMM at position 6 so ncu (-s 5 -c 1) profiles it.
// ============================================================================

constexpr int S = 2048, D = 1024, NB = 4;
constexpr long SD  = (long)S * D;
constexpr long SSZ = (long)S * S;
constexpr long NX = (long)NB * S * D;
constexpr long NW = (long)D * D;
constexpr long NP = (long)NB * S * S;

constexpr long OXH = 0,        OXL = NX;
constexpr long OWQH = 2*NX,    OWQL = OWQH+NW, OWKH = OWQH+2*NW, OWKL = OWQH+3*NW,
               OWVH = OWQH+4*NW, OWVL = OWQH+5*NW;
constexpr long OQH = 2*NX+6*NW, OQL = OQH+NX, OKH = OQH+2*NX, OKL = OQH+3*NX,
               OVTH = OQH+4*NX, OVTL = OQH+5*NX;
constexpr long OPH = OQH+6*NX,  OPL = OPH+NP;
constexpr long NBF = OPL + NP;

__device__ __align__(128) __nv_bfloat16 g_bf[NBF];
__device__ float g_sc[NP];

constexpr int STAGE  = 64 * 1024;          // AH|AL|BH|BL x 16KB
constexpr int OFF_AH = 0, OFF_AL = 16384, OFF_BH = 32768, OFF_BL = 49152;
constexpr int NSTG   = 3;
constexpr int SMEM_DYN = NSTG * STAGE + 1024;

#define SWZ(o) ((o) ^ (((o) >> 3) & 0x70))

// ---------------------------------------------------------------- helpers
__device__ __forceinline__ uint32_t smem_u32(const void* p) {
    uint32_t a;
    asm("{ .reg .u64 t; cvta.to.shared.u64 t, %1; cvt.u32.u64 %0, t; }"
        : "=r"(a) : "l"(p));
    return a;
}
__device__ __forceinline__ void ldsm4(uint32_t* r, uint32_t addr) {
    asm volatile("ldmatrix.sync.aligned.m8n8.x4.shared.b16 {%0,%1,%2,%3}, [%4];"
                 : "=r"(r[0]), "=r"(r[1]), "=r"(r[2]), "=r"(r[3]) : "r"(addr));
}
__device__ __forceinline__ void mma16816(float* d, const uint32_t* a,
                                         const uint32_t* b) {
    asm volatile(
        "mma.sync.aligned.m16n8k16.row.col.f32.bf16.bf16.f32 "
        "{%0,%1,%2,%3}, {%4,%5,%6,%7}, {%8,%9}, {%0,%1,%2,%3};"
        : "+f"(d[0]), "+f"(d[1]), "+f"(d[2]), "+f"(d[3])
        : "r"(a[0]), "r"(a[1]), "r"(a[2]), "r"(a[3]), "r"(b[0]), "r"(b[1]));
}
#define CPA16(dst, src) \
    asm volatile("cp.async.cg.shared.global [%0], [%1], 16;" \
                 :: "r"(dst), "l"(src) : "memory")
#define CP_COMMIT() asm volatile("cp.async.commit_group;" ::: "memory")

__device__ __forceinline__ void split2(float v0, float v1,
                                       uint32_t& h, uint32_t& l) {
    __nv_bfloat16 h0 = __float2bfloat16_rn(v0), h1 = __float2bfloat16_rn(v1);
    __nv_bfloat162 hh(h0, h1);
    __nv_bfloat162 ll(__float2bfloat16_rn(v0 - __bfloat162float(h0)),
                      __float2bfloat16_rn(v1 - __bfloat162float(h1)));
    h = *reinterpret_cast<uint32_t*>(&hh);
    l = *reinterpret_cast<uint32_t*>(&ll);
}

// ---------------------------------------------------------------- split
__global__ void __launch_bounds__(256)
split_arr(const float* __restrict__ in, __nv_bfloat16* __restrict__ oh,
          __nv_bfloat16* __restrict__ ol, long n)
{
    long i = ((long)blockIdx.x * 256 + threadIdx.x) * 4;
    if (i >= n) return;
    float4 v = *reinterpret_cast<const float4*>(in + i);
    uint2 h, l;
    split2(v.x, v.y, h.x, l.x);
    split2(v.z, v.w, h.y, l.y);
    *reinterpret_cast<uint2*>(oh + i) = h;
    *reinterpret_cast<uint2*>(ol + i) = l;
}

// ---------------------------------------------------------------- mainloop
// 512 thr, 16 warps (4m x 4n), warp 32x32, CTA 128x128, K-chunk 64, 3 stages.
// Pointers pre-offset to (row0/col0). acc[32].
__device__ __forceinline__ void gemm_mainloop(
    const __nv_bfloat16* __restrict__ gAh, const __nv_bfloat16* __restrict__ gAl,
    const __nv_bfloat16* __restrict__ gBh, const __nv_bfloat16* __restrict__ gBl,
    int lda, int ldb, int K, uint32_t abase, float* acc)
{
    const int tid = threadIdx.x, lane = tid & 31, wid = tid >> 5;

    // loader: r0 = row (0..63)[+64], s0 = 16B seg (0..7)
    const int r0 = tid >> 3, s0 = tid & 7;
    const uint32_t w0 = SWZ((uint32_t)r0 * 128 + s0 * 16);
    const uint32_t w1 = SWZ((uint32_t)(r0 + 64) * 128 + s0 * 16);
    const __nv_bfloat16* ga[8] = {
        gAh + (long)r0 * lda + s0 * 8,
        gAh + (long)(r0 + 64) * lda + s0 * 8,
        gAl + (long)r0 * lda + s0 * 8,
        gAl + (long)(r0 + 64) * lda + s0 * 8,
        gBh + (long)r0 * ldb + s0 * 8,
        gBh + (long)(r0 + 64) * ldb + s0 * 8,
        gBl + (long)r0 * ldb + s0 * 8,
        gBl + (long)(r0 + 64) * ldb + s0 * 8 };
    const uint32_t soff[8] = { OFF_AH + w0, OFF_AH + w1, OFF_AL + w0, OFF_AL + w1,
                               OFF_BH + w0, OFF_BH + w1, OFF_BL + w0, OFF_BL + w1 };

    // fragment constants (warp 32x32 at (mw,nw))
    const int mw = (wid >> 2) * 32, nw = (wid & 3) * 32;
    uint32_t a_row[2], a_swz[2];
#pragma unroll
    for (int i = 0; i < 2; i++) {
        uint32_t rb = (uint32_t)(mw + 16 * i + (lane & 15)) * 128;
        a_row[i] = rb; a_swz[i] = (rb >> 3) & 0x70;
    }
    const uint32_t a_kl = (uint32_t)((lane >> 4) << 4);
    uint32_t b_row[2], b_swz[2];
#pragma unroll
    for (int p = 0; p < 2; p++) {
        uint32_t rb = (uint32_t)(nw + 16 * p + (lane & 7) + ((lane & 16) >> 1)) * 128;
        b_row[p] = rb; b_swz[p] = (rb >> 3) & 0x70;
    }
    const uint32_t b_kl = (uint32_t)((lane & 8) << 1);

    const int nch = K >> 6;

#define ISSUE(ch) do {                                                        \
        const uint32_t _sb = abase + (uint32_t)((ch) % NSTG) * STAGE;         \
        const long _k = (long)(ch) * 64;                                      \
        _Pragma("unroll")                                                     \
        for (int q = 0; q < 8; q++) CPA16(_sb + soff[q], ga[q] + _k);         \
        CP_COMMIT();                                                          \
    } while (0)

    ISSUE(0);
    ISSUE(1);

    for (int ch = 0; ch < nch; ch++) {
        if (ch + 1 < nch)
            asm volatile("cp.async.wait_group 1;" ::: "memory");
        else
            asm volatile("cp.async.wait_group 0;" ::: "memory");
        __syncthreads();
        if (ch + 2 < nch) ISSUE(ch + 2);

        const uint32_t sb = abase + (uint32_t)(ch % NSTG) * STAGE;
#pragma unroll
        for (int ks = 0; ks < 4; ks++) {
            const uint32_t KB = ks * 32;
            uint32_t af[2][4], bh[8], bl[8];
#pragma unroll
            for (int i = 0; i < 2; i++)
                ldsm4(af[i], sb + OFF_AH + a_row[i] + ((KB + a_kl) ^ a_swz[i]));
#pragma unroll
            for (int p = 0; p < 2; p++) {
                const uint32_t ko = KB + b_kl;
                ldsm4(&bh[4 * p], sb + OFF_BH + b_row[p] + (ko ^ b_swz[p]));
                ldsm4(&bl[4 * p], sb + OFF_BL + b_row[p] + (ko ^ b_swz[p]));
            }
#pragma unroll
            for (int i = 0; i < 2; i++)
#pragma unroll
                for (int j = 0; j < 4; j++)
                    mma16816(acc + (i * 4 + j) * 4, af[i], &bh[j * 2]);  // hi*hi
#pragma unroll
            for (int i = 0; i < 2; i++)
#pragma unroll
                for (int j = 0; j < 4; j++)
                    mma16816(acc + (i * 4 + j) * 4, af[i], &bl[j * 2]);  // hi*lo
#pragma unroll
            for (int i = 0; i < 2; i++)   // reload A as lo (reuse regs)
                ldsm4(af[i], sb + OFF_AL + a_row[i] + ((KB + a_kl) ^ a_swz[i]));
#pragma unroll
            for (int i = 0; i < 2; i++)
#pragma unroll
                for (int j = 0; j < 4; j++)
                    mma16816(acc + (i * 4 + j) * 4, af[i], &bh[j * 2]);  // lo*hi
        }
    }
#undef ISSUE
}

// ---------------------------------------------------------------- fused QKV
// grid (D/128, NB*S/128, 3): z=0 Q, z=1 K (row-major bf16 pairs),
// z=2 VT (per-batch transposed pairs, ld = S, smem-staged).
__global__ void __launch_bounds__(512, 1)
mma_qkv(const float* __restrict__ bq, const float* __restrict__ bk,
        const float* __restrict__ bv)
{
    const int z = blockIdx.z;
    const long row0 = (long)blockIdx.y * 128, col0 = (long)blockIdx.x * 128;

    extern __shared__ char smem_raw[];
    const uint32_t rawb  = smem_u32(smem_raw);
    const uint32_t abase = (rawb + 1023) & ~1023u;
    char* smem = smem_raw + (abase - rawb);

    const __nv_bfloat16* Wh = &g_bf[z == 0 ? OWQH : z == 1 ? OWKH : OWVH];
    const __nv_bfloat16* Wl = &g_bf[z == 0 ? OWQL : z == 1 ? OWKL : OWVL];
    const float* bias = z == 0 ? bq : z == 1 ? bk : bv;

    float acc[32];
#pragma unroll
    for (int i = 0; i < 32; i++) acc[i] = 0.f;

    gemm_mainloop(&g_bf[OXH] + row0 * D, &g_bf[OXL] + row0 * D,
                  Wh + col0 * D, Wl + col0 * D, D, D, D, abase, acc);

    const int tid = threadIdx.x, lane = tid & 31, wid = tid >> 5;
    const int mw = (wid >> 2) * 32, nw = (wid & 3) * 32;
    const int qr = lane >> 2, qc = lane & 3;

    if (z < 2) {
        __nv_bfloat16* Ch = &g_bf[z == 0 ? OQH : OKH];
        __nv_bfloat16* Cl = &g_bf[z == 0 ? OQL : OKL];
#pragma unroll
        for (int i = 0; i < 2; i++)
#pragma unroll
            for (int j = 0; j < 4; j++) {
                const float* d = acc + (i * 4 + j) * 4;
#pragma unroll
                for (int h = 0; h < 2; h++) {
                    const long r = row0 + mw + 16 * i + qr + 8 * h;
                    const long c = col0 + nw + 8 * j + 2 * qc;
                    float v0 = d[2 * h] + bias[c], v1 = d[2 * h + 1] + bias[c + 1];
                    uint32_t hh, ll;
                    split2(v0, v1, hh, ll);
                    *reinterpret_cast<uint32_t*>(&Ch[r * D + c]) = hh;
                    *reinterpret_cast<uint32_t*>(&Cl[r * D + c]) = ll;
                }
            }
    } else {
        // VT: stage transposed tile in smem, coalesced 16B stores.
        const long b = row0 >> 11, rloc = row0 & (S - 1);
        __nv_bfloat16* Ch = &g_bf[OVTH] + b * SD;
        __nv_bfloat16* Cl = &g_bf[OVTL] + b * SD;
        __syncthreads();
        __nv_bfloat16* sh = reinterpret_cast<__nv_bfloat16*>(smem);
        __nv_bfloat16* sl = sh + 128 * 136;
#pragma unroll
        for (int i = 0; i < 2; i++)
#pragma unroll
            for (int j = 0; j < 4; j++) {
                const float* d = acc + (i * 4 + j) * 4;
#pragma unroll
                for (int h = 0; h < 2; h++) {
                    const int rl = mw + 16 * i + qr + 8 * h;
                    const int cl = nw + 8 * j + 2 * qc;
                    float v0 = d[2 * h] + bias[col0 + cl];
                    float v1 = d[2 * h + 1] + bias[col0 + cl + 1];
                    __nv_bfloat16 h0 = __float2bfloat16_rn(v0);
                    __nv_bfloat16 h1 = __float2bfloat16_rn(v1);
                    sh[cl * 136 + rl]       = h0;
                    sh[(cl + 1) * 136 + rl] = h1;
                    sl[cl * 136 + rl] =
                        __float2bfloat16_rn(v0 - __bfloat162float(h0));
                    sl[(cl + 1) * 136 + rl] =
                        __float2bfloat16_rn(v1 - __bfloat162float(h1));
                }
            }
        __syncthreads();
        const int c = tid >> 2, seg = tid & 3;   // 128 cols x 4 segs of 32 elems
        const __nv_bfloat16* srh = sh + c * 136 + seg * 32;
        const __nv_bfloat16* srl = sl + c * 136 + seg * 32;
        __nv_bfloat16* dsh = Ch + (col0 + c) * (long)S + rloc + seg * 32;
        __nv_bfloat16* dsl = Cl + (col0 + c) * (long)S + rloc + seg * 32;
#pragma unroll
        for (int q = 0; q < 4; q++) {
            *reinterpret_cast<uint4*>(dsh + q * 8) =
                *reinterpret_cast<const uint4*>(srh + q * 8);
            *reinterpret_cast<uint4*>(dsl + q * 8) =
                *reinterpret_cast<const uint4*>(srl + q * 8);
        }
    }
}

// ---------------------------------------------------------------- generic GEMM
// fp32 out: Cf[r*ldc + c] = scale * A@B^T. Batched by blockIdx.z.
__global__ void __launch_bounds__(512, 1)
mma_gemm(const __nv_bfloat16* __restrict__ Ah, const __nv_bfloat16* __restrict__ Al,
         const __nv_bfloat16* __restrict__ Bh, const __nv_bfloat16* __restrict__ Bl,
         float* __restrict__ Cf, int K, int lda, int ldb, int ldc,
         long sA, long sB, long sC, float scale)
{
    const long zb = blockIdx.z;
    const long row0 = (long)blockIdx.y * 128, col0 = (long)blockIdx.x * 128;

    extern __shared__ char smem_raw[];
    const uint32_t rawb  = smem_u32(smem_raw);
    const uint32_t abase = (rawb + 1023) & ~1023u;

    float acc[32];
#pragma unroll
    for (int i = 0; i < 32; i++) acc[i] = 0.f;

    gemm_mainloop(Ah + sA * zb + row0 * (long)lda, Al + sA * zb + row0 * (long)lda,
                  Bh + sB * zb + col0 * (long)ldb, Bl + sB * zb + col0 * (long)ldb,
                  lda, ldb, K, abase, acc);

    float* Cp = Cf + sC * zb;
    const int tid = threadIdx.x, lane = tid & 31, wid = tid >> 5;
    const int mw = (wid >> 2) * 32, nw = (wid & 3) * 32;
    const int qr = lane >> 2, qc = lane & 3;
#pragma unroll
    for (int i = 0; i < 2; i++)
#pragma unroll
        for (int j = 0; j < 4; j++) {
            const float* d = acc + (i * 4 + j) * 4;
#pragma unroll
            for (int h = 0; h < 2; h++) {
                const long r = row0 + mw + 16 * i + qr + 8 * h;
                const long c = col0 + nw + 8 * j + 2 * qc;
                *reinterpret_cast<float2*>(&Cp[r * (long)ldc + c]) =
                    make_float2(d[2 * h] * scale, d[2 * h + 1] * scale);
            }
        }
}

// ---------------------------------------------------------------- softmax
__global__ void __launch_bounds__(256)
softmax_rows(const float* __restrict__ sc, __nv_bfloat16* __restrict__ ph,
             __nv_bfloat16* __restrict__ pl)
{
    const long ro = (long)blockIdx.x * 2048;
    const float* p = sc + ro;
    __shared__ float red[8];
    const int t = threadIdx.x, lane = t & 31, w = t >> 5;

    float v[8];
    float m = -3.4e38f;
#pragma unroll
    for (int i = 0; i < 8; i++) { v[i] = p[t + (i << 8)]; m = fmaxf(m, v[i]); }
#pragma unroll
    for (int o = 16; o > 0; o >>= 1)
        m = fmaxf(m, __shfl_xor_sync(0xffffffffu, m, o));
    if (lane == 0) red[w] = m;
    __syncthreads();
    m = red[lane & 7];
#pragma unroll
    for (int o = 4; o > 0; o >>= 1)
        m = fmaxf(m, __shfl_xor_sync(0xffffffffu, m, o));

    float sum = 0.f;
#pragma unroll
    for (int i = 0; i < 8; i++) { v[i] = __expf(v[i] - m); sum += v[i]; }
#pragma unroll
    for (int o = 16; o > 0; o >>= 1)
        sum += __shfl_xor_sync(0xffffffffu, sum, o);
    __syncthreads();              // red[] reuse
    if (lane == 0) red[w] = sum;
    __syncthreads();
    sum = red[lane & 7];
#pragma unroll
    for (int o = 4; o > 0; o >>= 1)
        sum += __shfl_xor_sync(0xffffffffu, sum, o);
    const float inv = 1.f / sum;

#pragma unroll
    for (int i = 0; i < 8; i++) {
        float pv = v[i] * inv;
        __nv_bfloat16 h = __float2bfloat16_rn(pv);
        ph[ro + t + (i << 8)] = h;
        pl[ro + t + (i << 8)] = __float2bfloat16_rn(pv - __bfloat162float(h));
    }
}

// ---------------------------------------------------------------- launch
extern "C" void kernel_launch(void* const* d_in, const int* in_sizes, int n_in,
                              void* d_out, int out_size)
{
    const float* x  = (const float*)d_in[0];
    const float* Wq = (const float*)d_in[1];
    const float* bq = (const float*)d_in[2];
    const float* Wk = (const float*)d_in[3];
    const float* bk = (const float*)d_in[4];
    const float* Wv = (const float*)d_in[5];
    const float* bv = (const float*)d_in[6];
    float* out = (float*)d_out;

    __nv_bfloat16* bf; float* scp;
    cudaGetSymbolAddress((void**)&bf, g_bf);
    cudaGetSymbolAddress((void**)&scp, g_sc);

    cudaFuncSetAttribute(mma_qkv, cudaFuncAttributeMaxDynamicSharedMemorySize,
                         SMEM_DYN);
    cudaFuncSetAttribute(mma_gemm, cudaFuncAttributeMaxDynamicSharedMemorySize,
                         SMEM_DYN);
    dim3 thr(512);

    // launches 1-4: splits
    split_arr<<<(int)(NX / 1024), 256>>>(x,  bf + OXH,  bf + OXL,  NX);
    split_arr<<<(int)(NW / 1024), 256>>>(Wq, bf + OWQH, bf + OWQL, NW);
    split_arr<<<(int)(NW / 1024), 256>>>(Wk, bf + OWKH, bf + OWKL, NW);
    split_arr<<<(int)(NW / 1024), 256>>>(Wv, bf + OWVH, bf + OWVL, NW);

    // launch 5: fused Q/K/VT projections
    dim3 g_qkv(D / 128, (NB * S) / 128, 3);
    mma_qkv<<<g_qkv, thr, SMEM_DYN>>>(bq, bk, bv);

    // launch 6 (ncu target): Sc = Q@K^T / 32 (fp32), batched
    dim3 g_sc(S / 128, S / 128, NB);
    mma_gemm<<<g_sc, thr, SMEM_DYN>>>(bf+OQH, bf+OQL, bf+OKH, bf+OKL,
                                      scp, D, D, D, S, SD, SD, SSZ, 0.03125f);

    // launch 7: softmax -> P hi/lo
    softmax_rows<<<NB * S, 256>>>(scp, bf + OPH, bf + OPL);

    // launch 8: O = P@VT^T (fp32), batched, K = S
    dim3 g_o(D / 128, S / 128, NB);
    mma_gemm<<<g_o, thr, SMEM_DYN>>>(bf+OPH, bf+OPL, bf+OVTH, bf+OVTL,
                                     out, S, S, S, D, SSZ, SD, SD, 1.f);
}